// round 14
// baseline (speedup 1.0000x reference)
#include <cuda_runtime.h>
#include <cuda_fp16.h>
#include <cstdint>
#include <cstddef>

// Problem constants (fixed by the reference)
#define BB   2
#define NN   50000
#define EE   150000
#define FF   256
#define OUTD 256
#define RR   (BB * NN)       // 100000 rows
#define KTOT (3 * FF)        // 768
#define SEG  (4 * NN)        // 200000 segments
#define TOTE (4 * EE)        // 600000 CSR entries

#define NT1 48               // k16 bricks for W1
#define NT2 16               // k16 bricks for W2

// fp16 operand buffers
__device__ __half g_agg_h[(size_t)RR * 512];   // [r][0:256]=mi, [r][256:512]=mo
__device__ __half g_x_h[(size_t)RR * 256];     // X in fp16
// Fragment-packed weights, layout [nb][lane][t]: a lane's consecutive-t
// bricks are adjacent (8B each) -> LDG.128 fetches bricks (2p, 2p+1).
__device__ __half g_w1p[32 * NT1 * 128];
__device__ __half g_w2p[32 * NT2 * 128];

// CSR scratch (self-cleaning across calls)
__device__ int   g_count[SEG];
__device__ int   g_fill[SEG];
__device__ int   g_start[SEG];
__device__ int2  g_entry[TOTE];                // .x = src node, .y = weight bits

#define SCAN_TILE 2048
#define SCAN_NB   ((SEG + SCAN_TILE - 1) / SCAN_TILE)   // 98
__device__ volatile int g_scan_state[SCAN_NB];
__device__ int g_scan_agg[SCAN_NB];
__device__ int g_scan_incl[SCAN_NB];

// ---------------------------------------------------------------------------
// helpers
// ---------------------------------------------------------------------------
__device__ __forceinline__ float tanh_approx(float x) {
    float y;
    asm("tanh.approx.f32 %0, %1;" : "=f"(y) : "f"(x));
    return y;
}
__device__ __forceinline__ void cp16(uint32_t dst, const void* src, int bytes) {
    asm volatile("cp.async.cg.shared.global [%0], [%1], 16, %2;"
                 :: "r"(dst), "l"(src), "r"(bytes));
}
__device__ __forceinline__ uint32_t pack_h2(float lo, float hi) {
    __half2 h = __floats2half2_rn(lo, hi);
    return *reinterpret_cast<uint32_t*>(&h);
}
__device__ __forceinline__ void mma_f16(float c[4],
                                        uint32_t a0, uint32_t a1, uint32_t a2, uint32_t a3,
                                        uint32_t b0, uint32_t b1) {
    asm volatile(
        "mma.sync.aligned.m16n8k16.row.col.f32.f16.f16.f32 "
        "{%0,%1,%2,%3}, {%4,%5,%6,%7}, {%8,%9}, {%0,%1,%2,%3};"
        : "+f"(c[0]), "+f"(c[1]), "+f"(c[2]), "+f"(c[3])
        : "r"(a0), "r"(a1), "r"(a2), "r"(a3), "r"(b0), "r"(b1));
}

// ---------------------------------------------------------------------------
// 1) convx + count fused
// ---------------------------------------------------------------------------
__global__ void __launch_bounds__(256) convx_count_kernel(
    const float* __restrict__ X,
    const int* __restrict__ ri_idx,
    const int* __restrict__ ro_idx)
{
    const int t = blockIdx.x * blockDim.x + threadIdx.x;
    if (t < BB * EE) {
        int b = t / EE;
        atomicAdd(&g_count[(2 * b + 0) * NN + ri_idx[t]], 1);
        atomicAdd(&g_count[(2 * b + 1) * NN + ro_idx[t]], 1);
    }
    const size_t total = (size_t)RR * 256 / 8;
    uint4* dst = reinterpret_cast<uint4*>(g_x_h);
    const float4* src = reinterpret_cast<const float4*>(X);
    for (size_t i = (size_t)blockIdx.x * blockDim.x + threadIdx.x;
         i < total; i += (size_t)gridDim.x * blockDim.x) {
        float4 f0 = src[2 * i];
        float4 f1 = src[2 * i + 1];
        uint4 o;
        o.x = pack_h2(f0.x, f0.y); o.y = pack_h2(f0.z, f0.w);
        o.z = pack_h2(f1.x, f1.y); o.w = pack_h2(f1.z, f1.w);
        dst[i] = o;
    }
}

// ---------------------------------------------------------------------------
// 2) scan: decoupled lookback; re-zeros g_count
// ---------------------------------------------------------------------------
__global__ void __launch_bounds__(256) scan_kernel() {
    __shared__ int sh[256];
    __shared__ int s_off;
    const int bid = blockIdx.x;
    const int base = bid * SCAN_TILE + threadIdx.x * 8;

    int v[8]; int s = 0;
    #pragma unroll
    for (int j = 0; j < 8; j++) {
        int idx = base + j;
        int x = 0;
        if (idx < SEG) { x = g_count[idx]; g_count[idx] = 0; }
        v[j] = s;
        s += x;
    }
    sh[threadIdx.x] = s;
    __syncthreads();
    int acc = s;
    #pragma unroll
    for (int off = 1; off < 256; off <<= 1) {
        int t = (threadIdx.x >= off) ? sh[threadIdx.x - off] : 0;
        __syncthreads();
        acc += t;
        sh[threadIdx.x] = acc;
        __syncthreads();
    }
    const int excl_thread = acc - s;

    if (threadIdx.x == 255) {
        if (bid == 0) {
            g_scan_incl[0] = acc;
            __threadfence();
            g_scan_state[0] = 2;
            s_off = 0;
        } else {
            g_scan_agg[bid] = acc;
            __threadfence();
            g_scan_state[bid] = 1;
        }
    }
    if (bid > 0 && threadIdx.x == 0) {
        int off = 0;
        int j = bid - 1;
        while (true) {
            int st;
            do { st = g_scan_state[j]; } while (st == 0);
            __threadfence();
            if (st == 2) { off += g_scan_incl[j]; break; }
            off += g_scan_agg[j];
            j--;
        }
        s_off = off;
    }
    __syncthreads();
    const int off = s_off;
    if (bid > 0 && threadIdx.x == 255) {
        g_scan_incl[bid] = off + acc;
        __threadfence();
        g_scan_state[bid] = 2;
    }
    #pragma unroll
    for (int j = 0; j < 8; j++) {
        int idx = base + j;
        if (idx < SEG) g_start[idx] = off + excl_thread + v[j];
    }
}

// ---------------------------------------------------------------------------
// 3) fill CSR; resets scan flags
// ---------------------------------------------------------------------------
__global__ void fill_kernel(const float* __restrict__ e,
                            const int* __restrict__ ri_idx,
                            const int* __restrict__ ro_idx) {
    int t = blockIdx.x * blockDim.x + threadIdx.x;
    if (t < SCAN_NB) g_scan_state[t] = 0;
    if (t >= BB * EE) return;
    int b = t / EE;
    float w = e[t];
    int ri = ri_idx[t];
    int ro = ro_idx[t];
    int s0 = (2 * b + 0) * NN + ri;
    int s1 = (2 * b + 1) * NN + ro;
    int p0 = g_start[s0] + atomicAdd(&g_fill[s0], 1);
    g_entry[p0] = make_int2(ro, __float_as_int(w));
    int p1 = g_start[s1] + atomicAdd(&g_fill[s1], 1);
    g_entry[p1] = make_int2(ri, __float_as_int(w));
}

// ---------------------------------------------------------------------------
// 4) gather on fp16 X (R10 version — measured best)
// ---------------------------------------------------------------------------
__device__ __forceinline__ void fma8(float a[8], float w, const uint4& r) {
    const __half2* h = reinterpret_cast<const __half2*>(&r);
    #pragma unroll
    for (int i = 0; i < 4; i++) {
        float2 f = __half22float2(h[i]);
        a[2 * i]     = fmaf(w, f.x, a[2 * i]);
        a[2 * i + 1] = fmaf(w, f.y, a[2 * i + 1]);
    }
}

__global__ void __launch_bounds__(256) gather_kernel() {
    int wt = blockIdx.x * 8 + (threadIdx.x >> 5);
    if (wt >= SEG / 2) return;
    int lane = threadIdx.x & 31;
    int segA = wt * 2;
    int segB = segA + 1;

    int arrA = segA / NN, nA = segA - arrA * NN;
    int arrB = segB / NN, nB = segB - arrB * NN;

    int sA = g_start[segA];
    int sB = g_start[segB];
    int c = 0;
    if (lane < 2) { c = g_fill[segA + lane]; g_fill[segA + lane] = 0; }
    int cA = __shfl_sync(0xffffffffu, c, 0);
    int cB = __shfl_sync(0xffffffffu, c, 1);

    const uint4* XA = reinterpret_cast<const uint4*>(g_x_h + (size_t)(arrA >> 1) * NN * FF);
    const uint4* XB = reinterpret_cast<const uint4*>(g_x_h + (size_t)(arrB >> 1) * NN * FF);

    float aA[8] = {0.f, 0.f, 0.f, 0.f, 0.f, 0.f, 0.f, 0.f};
    float aB[8] = {0.f, 0.f, 0.f, 0.f, 0.f, 0.f, 0.f, 0.f};
    const uint4 z4 = make_uint4(0, 0, 0, 0);

    int iA = sA, eA = sA + cA;
    int iB = sB, eB = sB + cB;
    while (iA < eA || iB < eB) {
        bool pA0 = iA < eA,     pA1 = iA + 1 < eA;
        bool pB0 = iB < eB,     pB1 = iB + 1 < eB;
        int2 eA0 = make_int2(0, 0), eA1 = make_int2(0, 0);
        int2 eB0 = make_int2(0, 0), eB1 = make_int2(0, 0);
        if (pA0) eA0 = g_entry[iA];
        if (pA1) eA1 = g_entry[iA + 1];
        if (pB0) eB0 = g_entry[iB];
        if (pB1) eB1 = g_entry[iB + 1];

        uint4 rA0 = z4, rA1 = z4, rB0 = z4, rB1 = z4;
        if (pA0) rA0 = XA[(size_t)eA0.x * 32 + lane];
        if (pA1) rA1 = XA[(size_t)eA1.x * 32 + lane];
        if (pB0) rB0 = XB[(size_t)eB0.x * 32 + lane];
        if (pB1) rB1 = XB[(size_t)eB1.x * 32 + lane];

        fma8(aA, pA0 ? __int_as_float(eA0.y) : 0.f, rA0);
        fma8(aA, pA1 ? __int_as_float(eA1.y) : 0.f, rA1);
        fma8(aB, pB0 ? __int_as_float(eB0.y) : 0.f, rB0);
        fma8(aB, pB1 ? __int_as_float(eB1.y) : 0.f, rB1);
        iA += 2; iB += 2;
    }

    uint4 oA, oB;
    oA.x = pack_h2(aA[0], aA[1]); oA.y = pack_h2(aA[2], aA[3]);
    oA.z = pack_h2(aA[4], aA[5]); oA.w = pack_h2(aA[6], aA[7]);
    oB.x = pack_h2(aB[0], aB[1]); oB.y = pack_h2(aB[2], aB[3]);
    oB.z = pack_h2(aB[4], aB[5]); oB.w = pack_h2(aB[6], aB[7]);

    __half* dA = g_agg_h + ((size_t)(arrA >> 1) * NN + nA) * 512 + (arrA & 1) * 256;
    __half* dB = g_agg_h + ((size_t)(arrB >> 1) * NN + nB) * 512 + (arrB & 1) * 256;
    *reinterpret_cast<uint4*>(dA + 8 * lane) = oA;
    *reinterpret_cast<uint4*>(dB + 8 * lane) = oB;
}

// ---------------------------------------------------------------------------
// 5/6) pack W[K][N] fp32 -> fragment bricks fp16, layout [nb][lane][t]
// ---------------------------------------------------------------------------
__global__ void convw_pack_kernel(const float* __restrict__ W, __half* __restrict__ out,
                                  int K, int N) {
    int idx = blockIdx.x * blockDim.x + threadIdx.x;
    int nkb = K / 16;
    int total = (N / 8) * nkb * 32;
    if (idx >= total) return;
    int lane = idx & 31;
    int brick = idx >> 5;
    int nb = brick / nkb;
    int kb = brick - nb * nkb;
    int g = lane >> 2, tg = lane & 3;
    int n = nb * 8 + g;
    int k0 = kb * 16 + 2 * tg;
    __half h[4];
    h[0] = __float2half_rn(W[(size_t)(k0    ) * N + n]);
    h[1] = __float2half_rn(W[(size_t)(k0 + 1) * N + n]);
    h[2] = __float2half_rn(W[(size_t)(k0 + 8) * N + n]);
    h[3] = __float2half_rn(W[(size_t)(k0 + 9) * N + n]);
    size_t o = ((size_t)(nb * 32 + lane) * nkb + kb) * 4;   // [nb][lane][t]
    *reinterpret_cast<uint2*>(out + o) = *reinterpret_cast<uint2*>(h);
}

// ---------------------------------------------------------------------------
// 7) Fused 2-layer MLP, fp16 m16n8k16, 512 threads, K-chunk 32.
// A: 4-stage cp.async ring (stage = 128 rows x 40 halves = 10240 B; all 512
//    threads stage 1 x 16B; frag word-stride 20 -> banks 20g+tg distinct).
// B: one LDG.128 per (warp, nt) per k32 iter fetches BOTH k16 bricks
//    ([nb][lane][t] packing), issued before the stage wait -> L2 latency
//    hidden behind wait + first-half MMAs. 24 barrier rounds instead of 48.
// ---------------------------------------------------------------------------
#define GBM 128
#define NST 4
#define A_LDH 40
#define C_LDH 280
#define A_STG_B (GBM * A_LDH * 2)                 // 10240 B
#define CS_OFF  (NST * A_STG_B)                   // 40960
#define SMEM_BYTES (CS_OFF + GBM * C_LDH * 2)     // 112640

__global__ void __launch_bounds__(512, 1) fused_mlp_kernel(
    const float* __restrict__ b1,
    const float* __restrict__ b2,
    float* __restrict__ Out,
    int rows)
{
    extern __shared__ char smem[];
    const uint32_t smem_u = (uint32_t)__cvta_generic_to_shared(smem);
    const uint32_t* Asw = reinterpret_cast<const uint32_t*>(smem);
    uint32_t* Csw = reinterpret_cast<uint32_t*>(smem + CS_OFF);

    const int tid  = threadIdx.x;
    const int warp = tid >> 5;
    const int lane = tid & 31;
    const int g    = lane >> 2;
    const int tg   = lane & 3;
    const int wm   = warp & 3;         // M group (32 rows)
    const int wn   = warp >> 2;        // N group (64 cols)
    const int rowBase = blockIdx.x * GBM;

    const uint4* w1q = reinterpret_cast<const uint4*>(g_w1p);
    const uint4* w2q = reinterpret_cast<const uint4*>(g_w2p);

    float acc[2][8][4];
    #pragma unroll
    for (int mt = 0; mt < 2; mt++)
        #pragma unroll
        for (int nt = 0; nt < 8; nt++)
            #pragma unroll
            for (int r = 0; r < 4; r++) acc[mt][nt][r] = 0.f;

    // A loader: k32 tile = 128 rows x 32 halves = 512 x 16B -> 1 per thread
    auto load_tileA = [&](int st, int t32) {
        const int k0 = t32 * 32;
        const int row = tid >> 2;
        const int kc  = (tid & 3) * 8;
        const int gr  = rowBase + row;
        const __half* asrc = (k0 < 512)
            ? g_agg_h + (size_t)gr * 512 + (k0 + kc)
            : g_x_h   + (size_t)gr * 256 + (k0 - 512 + kc);
        cp16(smem_u + (uint32_t)(st * A_STG_B + (row * A_LDH + kc) * 2),
             asrc, gr < rows ? 16 : 0);
    };

    #pragma unroll
    for (int t = 0; t < NST - 1; t++) {
        load_tileA(t, t);
        asm volatile("cp.async.commit_group;");
    }

    // ================= Phase 1: 24 x k32, [agg|X] @ W1 =================
    for (int t32 = 0; t32 < NT1 / 2; t32++) {
        // B for both k16 halves of this k32 chunk: one LDG.128 per nt
        uint4 bfr[8];
        #pragma unroll
        for (int nt = 0; nt < 8; nt++)
            bfr[nt] = w1q[(size_t)((wn * 8 + nt) * 32 + lane) * (NT1 / 2) + t32];

        asm volatile("cp.async.wait_group %0;" :: "n"(NST - 2));
        __syncthreads();
        const int st = t32 & (NST - 1);
        {
            const int tn = t32 + NST - 1;
            if (tn < NT1 / 2) load_tileA(tn & (NST - 1), tn);
            asm volatile("cp.async.commit_group;");
        }
        const uint32_t* Aw = Asw + st * (A_STG_B / 4);

        #pragma unroll
        for (int ks = 0; ks < 2; ks++) {
            const int kw = ks * 8;
            uint32_t a[2][4];
            #pragma unroll
            for (int mt = 0; mt < 2; mt++) {
                const int r = wm * 32 + mt * 16 + g;
                a[mt][0] = Aw[(r    ) * 20 + kw + tg    ];
                a[mt][1] = Aw[(r + 8) * 20 + kw + tg    ];
                a[mt][2] = Aw[(r    ) * 20 + kw + tg + 4];
                a[mt][3] = Aw[(r + 8) * 20 + kw + tg + 4];
            }
            #pragma unroll
            for (int mt = 0; mt < 2; mt++)
                #pragma unroll
                for (int nt = 0; nt < 8; nt++)
                    mma_f16(acc[mt][nt], a[mt][0], a[mt][1], a[mt][2], a[mt][3],
                            ks ? bfr[nt].z : bfr[nt].x,
                            ks ? bfr[nt].w : bfr[nt].y);
        }
    }

    // ---- epilogue 1: bias + tanh -> Cs fp16 ----
    __syncthreads();
    #pragma unroll
    for (int mt = 0; mt < 2; mt++) {
        const int r0 = wm * 32 + mt * 16 + g;
        #pragma unroll
        for (int nt = 0; nt < 8; nt++) {
            const int col = wn * 64 + nt * 8 + tg * 2;
            const float bb0 = b1[col];
            const float bb1 = b1[col + 1];
            Csw[(r0    ) * 140 + (col >> 1)] =
                pack_h2(tanh_approx(acc[mt][nt][0] + bb0),
                        tanh_approx(acc[mt][nt][1] + bb1));
            Csw[(r0 + 8) * 140 + (col >> 1)] =
                pack_h2(tanh_approx(acc[mt][nt][2] + bb0),
                        tanh_approx(acc[mt][nt][3] + bb1));
            acc[mt][nt][0] = 0.f; acc[mt][nt][1] = 0.f;
            acc[mt][nt][2] = 0.f; acc[mt][nt][3] = 0.f;
        }
    }
    __syncthreads();

    // ================= Phase 2: 8 x k32, Cs @ W2 =================
    for (int p = 0; p < NT2 / 2; p++) {
        uint4 bfr[8];
        #pragma unroll
        for (int nt = 0; nt < 8; nt++)
            bfr[nt] = w2q[(size_t)((wn * 8 + nt) * 32 + lane) * (NT2 / 2) + p];

        #pragma unroll
        for (int ks = 0; ks < 2; ks++) {
            const int kw = (2 * p + ks) * 8;
            uint32_t a[2][4];
            #pragma unroll
            for (int mt = 0; mt < 2; mt++) {
                const int r = wm * 32 + mt * 16 + g;
                a[mt][0] = Csw[(r    ) * 140 + kw + tg    ];
                a[mt][1] = Csw[(r + 8) * 140 + kw + tg    ];
                a[mt][2] = Csw[(r    ) * 140 + kw + tg + 4];
                a[mt][3] = Csw[(r + 8) * 140 + kw + tg + 4];
            }
            #pragma unroll
            for (int mt = 0; mt < 2; mt++)
                #pragma unroll
                for (int nt = 0; nt < 8; nt++)
                    mma_f16(acc[mt][nt], a[mt][0], a[mt][1], a[mt][2], a[mt][3],
                            ks ? bfr[nt].z : bfr[nt].x,
                            ks ? bfr[nt].w : bfr[nt].y);
        }
    }

    // ---- epilogue 2: bias + tanh -> global fp32 ----
    #pragma unroll
    for (int mt = 0; mt < 2; mt++) {
        const int r0 = rowBase + wm * 32 + mt * 16 + g;
        #pragma unroll
        for (int nt = 0; nt < 8; nt++) {
            const int col = wn * 64 + nt * 8 + tg * 2;
            const float bb0 = b2[col];
            const float bb1 = b2[col + 1];
            if (r0 < rows) {
                float2 v;
                v.x = tanh_approx(acc[mt][nt][0] + bb0);
                v.y = tanh_approx(acc[mt][nt][1] + bb1);
                *reinterpret_cast<float2*>(Out + (size_t)r0 * 256 + col) = v;
            }
            if (r0 + 8 < rows) {
                float2 v;
                v.x = tanh_approx(acc[mt][nt][2] + bb0);
                v.y = tanh_approx(acc[mt][nt][3] + bb1);
                *reinterpret_cast<float2*>(Out + (size_t)(r0 + 8) * 256 + col) = v;
            }
        }
    }
}

// ---------------------------------------------------------------------------
// Launcher. Inputs (metadata order): X, e, ri_idx, ro_idx, W1, b1, W2, b2
// ---------------------------------------------------------------------------
extern "C" void kernel_launch(void* const* d_in, const int* in_sizes, int n_in,
                              void* d_out, int out_size)
{
    (void)in_sizes; (void)n_in; (void)out_size;

    const float* X  = (const float*)d_in[0];
    const float* e  = (const float*)d_in[1];
    const int*   ri = (const int*)  d_in[2];
    const int*   ro = (const int*)  d_in[3];
    const float* W1 = (const float*)d_in[4];
    const float* b1 = (const float*)d_in[5];
    const float* W2 = (const float*)d_in[6];
    const float* b2 = (const float*)d_in[7];
    float* out = (float*)d_out;

    __half *w1p_ptr = nullptr, *w2p_ptr = nullptr;
    cudaGetSymbolAddress((void**)&w1p_ptr, g_w1p);
    cudaGetSymbolAddress((void**)&w2p_ptr, g_w2p);

    cudaFuncSetAttribute(fused_mlp_kernel,
                         cudaFuncAttributeMaxDynamicSharedMemorySize, SMEM_BYTES);

    // 1: convx+count, 2: scan, 3: fill, 4: gather (profiled)
    convx_count_kernel<<<(BB * EE + 255) / 256, 256>>>(X, ri, ro);
    scan_kernel<<<SCAN_NB, 256>>>();
    fill_kernel<<<(BB * EE + 255) / 256, 256>>>(e, ri, ro);
    gather_kernel<<<(SEG / 2) / 8, 256>>>();

    // 5/6: weight fragment packing
    convw_pack_kernel<<<(32 * NT1 * 32 + 255) / 256, 256>>>(W1, w1p_ptr, KTOT, 256);
    convw_pack_kernel<<<(32 * NT2 * 32 + 255) / 256, 256>>>(W2, w2p_ptr, 256, 256);

    // 7: fused MLP
    const int nblk = (RR + GBM - 1) / GBM;    // 782
    fused_mlp_kernel<<<nblk, 512, SMEM_BYTES>>>(b1, b2, out, RR);
}

// round 15
// speedup vs baseline: 1.9094x; 1.9094x over previous
#include <cuda_runtime.h>
#include <cuda_fp16.h>
#include <cstdint>
#include <cstddef>

// Problem constants (fixed by the reference)
#define BB   2
#define NN   50000
#define EE   150000
#define FF   256
#define OUTD 256
#define RR   (BB * NN)       // 100000 rows
#define KTOT (3 * FF)        // 768
#define SEG  (4 * NN)        // 200000 segments
#define TOTE (4 * EE)        // 600000 CSR entries

#define NT1 48               // k16 bricks for W1
#define NT2 16               // k16 bricks for W2
#define NP1 (NT1 / 2)        // 24 k32 chunks
#define NP2 (NT2 / 2)        // 8

// fp16 operand buffers
__device__ __half g_agg_h[(size_t)RR * 512];   // [r][0:256]=mi, [r][256:512]=mo
__device__ __half g_x_h[(size_t)RR * 256];     // X in fp16
// Fragment-packed weights, layout [nb][t32][lane][2 bricks of 4 halves]:
// a (nb,t32) group = 32 lanes x 16B CONTIGUOUS (coalesced LDG.128);
// lane's uint4 = {brick 2*t32 (8B), brick 2*t32+1 (8B)}.
__device__ __half g_w1p[32 * NT1 * 128];
__device__ __half g_w2p[32 * NT2 * 128];

// CSR scratch (self-cleaning across calls)
__device__ int   g_count[SEG];
__device__ int   g_fill[SEG];
__device__ int   g_start[SEG];
__device__ int2  g_entry[TOTE];                // .x = src node, .y = weight bits

#define SCAN_TILE 2048
#define SCAN_NB   ((SEG + SCAN_TILE - 1) / SCAN_TILE)   // 98
__device__ volatile int g_scan_state[SCAN_NB];
__device__ int g_scan_agg[SCAN_NB];
__device__ int g_scan_incl[SCAN_NB];

// ---------------------------------------------------------------------------
// helpers
// ---------------------------------------------------------------------------
__device__ __forceinline__ float tanh_approx(float x) {
    float y;
    asm("tanh.approx.f32 %0, %1;" : "=f"(y) : "f"(x));
    return y;
}
__device__ __forceinline__ void cp16(uint32_t dst, const void* src, int bytes) {
    asm volatile("cp.async.cg.shared.global [%0], [%1], 16, %2;"
                 :: "r"(dst), "l"(src), "r"(bytes));
}
__device__ __forceinline__ uint32_t pack_h2(float lo, float hi) {
    __half2 h = __floats2half2_rn(lo, hi);
    return *reinterpret_cast<uint32_t*>(&h);
}
__device__ __forceinline__ void mma_f16(float c[4],
                                        uint32_t a0, uint32_t a1, uint32_t a2, uint32_t a3,
                                        uint32_t b0, uint32_t b1) {
    asm volatile(
        "mma.sync.aligned.m16n8k16.row.col.f32.f16.f16.f32 "
        "{%0,%1,%2,%3}, {%4,%5,%6,%7}, {%8,%9}, {%0,%1,%2,%3};"
        : "+f"(c[0]), "+f"(c[1]), "+f"(c[2]), "+f"(c[3])
        : "r"(a0), "r"(a1), "r"(a2), "r"(a3), "r"(b0), "r"(b1));
}

// ---------------------------------------------------------------------------
// 1) convx + count fused
// ---------------------------------------------------------------------------
__global__ void __launch_bounds__(256) convx_count_kernel(
    const float* __restrict__ X,
    const int* __restrict__ ri_idx,
    const int* __restrict__ ro_idx)
{
    const int t = blockIdx.x * blockDim.x + threadIdx.x;
    if (t < BB * EE) {
        int b = t / EE;
        atomicAdd(&g_count[(2 * b + 0) * NN + ri_idx[t]], 1);
        atomicAdd(&g_count[(2 * b + 1) * NN + ro_idx[t]], 1);
    }
    const size_t total = (size_t)RR * 256 / 8;
    uint4* dst = reinterpret_cast<uint4*>(g_x_h);
    const float4* src = reinterpret_cast<const float4*>(X);
    for (size_t i = (size_t)blockIdx.x * blockDim.x + threadIdx.x;
         i < total; i += (size_t)gridDim.x * blockDim.x) {
        float4 f0 = src[2 * i];
        float4 f1 = src[2 * i + 1];
        uint4 o;
        o.x = pack_h2(f0.x, f0.y); o.y = pack_h2(f0.z, f0.w);
        o.z = pack_h2(f1.x, f1.y); o.w = pack_h2(f1.z, f1.w);
        dst[i] = o;
    }
}

// ---------------------------------------------------------------------------
// 2) scan: decoupled lookback; re-zeros g_count
// ---------------------------------------------------------------------------
__global__ void __launch_bounds__(256) scan_kernel() {
    __shared__ int sh[256];
    __shared__ int s_off;
    const int bid = blockIdx.x;
    const int base = bid * SCAN_TILE + threadIdx.x * 8;

    int v[8]; int s = 0;
    #pragma unroll
    for (int j = 0; j < 8; j++) {
        int idx = base + j;
        int x = 0;
        if (idx < SEG) { x = g_count[idx]; g_count[idx] = 0; }
        v[j] = s;
        s += x;
    }
    sh[threadIdx.x] = s;
    __syncthreads();
    int acc = s;
    #pragma unroll
    for (int off = 1; off < 256; off <<= 1) {
        int t = (threadIdx.x >= off) ? sh[threadIdx.x - off] : 0;
        __syncthreads();
        acc += t;
        sh[threadIdx.x] = acc;
        __syncthreads();
    }
    const int excl_thread = acc - s;

    if (threadIdx.x == 255) {
        if (bid == 0) {
            g_scan_incl[0] = acc;
            __threadfence();
            g_scan_state[0] = 2;
            s_off = 0;
        } else {
            g_scan_agg[bid] = acc;
            __threadfence();
            g_scan_state[bid] = 1;
        }
    }
    if (bid > 0 && threadIdx.x == 0) {
        int off = 0;
        int j = bid - 1;
        while (true) {
            int st;
            do { st = g_scan_state[j]; } while (st == 0);
            __threadfence();
            if (st == 2) { off += g_scan_incl[j]; break; }
            off += g_scan_agg[j];
            j--;
        }
        s_off = off;
    }
    __syncthreads();
    const int off = s_off;
    if (bid > 0 && threadIdx.x == 255) {
        g_scan_incl[bid] = off + acc;
        __threadfence();
        g_scan_state[bid] = 2;
    }
    #pragma unroll
    for (int j = 0; j < 8; j++) {
        int idx = base + j;
        if (idx < SEG) g_start[idx] = off + excl_thread + v[j];
    }
}

// ---------------------------------------------------------------------------
// 3) fill CSR; resets scan flags
// ---------------------------------------------------------------------------
__global__ void fill_kernel(const float* __restrict__ e,
                            const int* __restrict__ ri_idx,
                            const int* __restrict__ ro_idx) {
    int t = blockIdx.x * blockDim.x + threadIdx.x;
    if (t < SCAN_NB) g_scan_state[t] = 0;
    if (t >= BB * EE) return;
    int b = t / EE;
    float w = e[t];
    int ri = ri_idx[t];
    int ro = ro_idx[t];
    int s0 = (2 * b + 0) * NN + ri;
    int s1 = (2 * b + 1) * NN + ro;
    int p0 = g_start[s0] + atomicAdd(&g_fill[s0], 1);
    g_entry[p0] = make_int2(ro, __float_as_int(w));
    int p1 = g_start[s1] + atomicAdd(&g_fill[s1], 1);
    g_entry[p1] = make_int2(ri, __float_as_int(w));
}

// ---------------------------------------------------------------------------
// 4) gather on fp16 X (R10 version — measured best)
// ---------------------------------------------------------------------------
__device__ __forceinline__ void fma8(float a[8], float w, const uint4& r) {
    const __half2* h = reinterpret_cast<const __half2*>(&r);
    #pragma unroll
    for (int i = 0; i < 4; i++) {
        float2 f = __half22float2(h[i]);
        a[2 * i]     = fmaf(w, f.x, a[2 * i]);
        a[2 * i + 1] = fmaf(w, f.y, a[2 * i + 1]);
    }
}

__global__ void __launch_bounds__(256) gather_kernel() {
    int wt = blockIdx.x * 8 + (threadIdx.x >> 5);
    if (wt >= SEG / 2) return;
    int lane = threadIdx.x & 31;
    int segA = wt * 2;
    int segB = segA + 1;

    int arrA = segA / NN, nA = segA - arrA * NN;
    int arrB = segB / NN, nB = segB - arrB * NN;

    int sA = g_start[segA];
    int sB = g_start[segB];
    int c = 0;
    if (lane < 2) { c = g_fill[segA + lane]; g_fill[segA + lane] = 0; }
    int cA = __shfl_sync(0xffffffffu, c, 0);
    int cB = __shfl_sync(0xffffffffu, c, 1);

    const uint4* XA = reinterpret_cast<const uint4*>(g_x_h + (size_t)(arrA >> 1) * NN * FF);
    const uint4* XB = reinterpret_cast<const uint4*>(g_x_h + (size_t)(arrB >> 1) * NN * FF);

    float aA[8] = {0.f, 0.f, 0.f, 0.f, 0.f, 0.f, 0.f, 0.f};
    float aB[8] = {0.f, 0.f, 0.f, 0.f, 0.f, 0.f, 0.f, 0.f};
    const uint4 z4 = make_uint4(0, 0, 0, 0);

    int iA = sA, eA = sA + cA;
    int iB = sB, eB = sB + cB;
    while (iA < eA || iB < eB) {
        bool pA0 = iA < eA,     pA1 = iA + 1 < eA;
        bool pB0 = iB < eB,     pB1 = iB + 1 < eB;
        int2 eA0 = make_int2(0, 0), eA1 = make_int2(0, 0);
        int2 eB0 = make_int2(0, 0), eB1 = make_int2(0, 0);
        if (pA0) eA0 = g_entry[iA];
        if (pA1) eA1 = g_entry[iA + 1];
        if (pB0) eB0 = g_entry[iB];
        if (pB1) eB1 = g_entry[iB + 1];

        uint4 rA0 = z4, rA1 = z4, rB0 = z4, rB1 = z4;
        if (pA0) rA0 = XA[(size_t)eA0.x * 32 + lane];
        if (pA1) rA1 = XA[(size_t)eA1.x * 32 + lane];
        if (pB0) rB0 = XB[(size_t)eB0.x * 32 + lane];
        if (pB1) rB1 = XB[(size_t)eB1.x * 32 + lane];

        fma8(aA, pA0 ? __int_as_float(eA0.y) : 0.f, rA0);
        fma8(aA, pA1 ? __int_as_float(eA1.y) : 0.f, rA1);
        fma8(aB, pB0 ? __int_as_float(eB0.y) : 0.f, rB0);
        fma8(aB, pB1 ? __int_as_float(eB1.y) : 0.f, rB1);
        iA += 2; iB += 2;
    }

    uint4 oA, oB;
    oA.x = pack_h2(aA[0], aA[1]); oA.y = pack_h2(aA[2], aA[3]);
    oA.z = pack_h2(aA[4], aA[5]); oA.w = pack_h2(aA[6], aA[7]);
    oB.x = pack_h2(aB[0], aB[1]); oB.y = pack_h2(aB[2], aB[3]);
    oB.z = pack_h2(aB[4], aB[5]); oB.w = pack_h2(aB[6], aB[7]);

    __half* dA = g_agg_h + ((size_t)(arrA >> 1) * NN + nA) * 512 + (arrA & 1) * 256;
    __half* dB = g_agg_h + ((size_t)(arrB >> 1) * NN + nB) * 512 + (arrB & 1) * 256;
    *reinterpret_cast<uint4*>(dA + 8 * lane) = oA;
    *reinterpret_cast<uint4*>(dB + 8 * lane) = oB;
}

// ---------------------------------------------------------------------------
// 5/6) pack W[K][N] fp32 -> fragment bricks fp16, layout [nb][t32][lane][pair]
// ---------------------------------------------------------------------------
__global__ void convw_pack_kernel(const float* __restrict__ W, __half* __restrict__ out,
                                  int K, int N) {
    int idx = blockIdx.x * blockDim.x + threadIdx.x;
    int nkb = K / 16;
    int total = (N / 8) * nkb * 32;
    if (idx >= total) return;
    int lane = idx & 31;
    int brick = idx >> 5;
    int nb = brick / nkb;
    int kb = brick - nb * nkb;
    int g = lane >> 2, tg = lane & 3;
    int n = nb * 8 + g;
    int k0 = kb * 16 + 2 * tg;
    __half h[4];
    h[0] = __float2half_rn(W[(size_t)(k0    ) * N + n]);
    h[1] = __float2half_rn(W[(size_t)(k0 + 1) * N + n]);
    h[2] = __float2half_rn(W[(size_t)(k0 + 8) * N + n]);
    h[3] = __float2half_rn(W[(size_t)(k0 + 9) * N + n]);
    // [nb][t32][lane][pair]: t32 = kb/2, pair slot = kb&1 (4 halves each)
    size_t o = (((size_t)nb * (nkb / 2) + (kb >> 1)) * 32 + lane) * 8 + (kb & 1) * 4;
    *reinterpret_cast<uint2*>(out + o) = *reinterpret_cast<uint2*>(h);
}

// ---------------------------------------------------------------------------
// 7) Fused 2-layer MLP, fp16 m16n8k16, 512 threads, K-chunk 32.
// A: 4-stage cp.async ring (stage = 128 rows x 40 halves = 10240 B; 512
//    threads stage 1 x 16B each; frag word-stride 20 -> banks 20g+tg distinct).
// B: one COALESCED LDG.128 per (warp, nt) per k32 iter (lane-contiguous
//    512B/warp), issued before the stage wait. 24 barrier rounds vs 48.
// ---------------------------------------------------------------------------
#define GBM 128
#define NST 4
#define A_LDH 40
#define C_LDH 280
#define A_STG_B (GBM * A_LDH * 2)                 // 10240 B
#define CS_OFF  (NST * A_STG_B)                   // 40960
#define SMEM_BYTES (CS_OFF + GBM * C_LDH * 2)     // 112640

__global__ void __launch_bounds__(512, 1) fused_mlp_kernel(
    const float* __restrict__ b1,
    const float* __restrict__ b2,
    float* __restrict__ Out,
    int rows)
{
    extern __shared__ char smem[];
    const uint32_t smem_u = (uint32_t)__cvta_generic_to_shared(smem);
    const uint32_t* Asw = reinterpret_cast<const uint32_t*>(smem);
    uint32_t* Csw = reinterpret_cast<uint32_t*>(smem + CS_OFF);

    const int tid  = threadIdx.x;
    const int warp = tid >> 5;
    const int lane = tid & 31;
    const int g    = lane >> 2;
    const int tg   = lane & 3;
    const int wm   = warp & 3;         // M group (32 rows)
    const int wn   = warp >> 2;        // N group (64 cols)
    const int rowBase = blockIdx.x * GBM;

    const uint4* w1q = reinterpret_cast<const uint4*>(g_w1p);
    const uint4* w2q = reinterpret_cast<const uint4*>(g_w2p);

    float acc[2][8][4];
    #pragma unroll
    for (int mt = 0; mt < 2; mt++)
        #pragma unroll
        for (int nt = 0; nt < 8; nt++)
            #pragma unroll
            for (int r = 0; r < 4; r++) acc[mt][nt][r] = 0.f;

    // A loader: k32 tile = 128 rows x 32 halves = 512 x 16B -> 1 per thread
    auto load_tileA = [&](int st, int t32) {
        const int k0 = t32 * 32;
        const int row = tid >> 2;
        const int kc  = (tid & 3) * 8;
        const int gr  = rowBase + row;
        const __half* asrc = (k0 < 512)
            ? g_agg_h + (size_t)gr * 512 + (k0 + kc)
            : g_x_h   + (size_t)gr * 256 + (k0 - 512 + kc);
        cp16(smem_u + (uint32_t)(st * A_STG_B + (row * A_LDH + kc) * 2),
             asrc, gr < rows ? 16 : 0);
    };

    #pragma unroll
    for (int t = 0; t < NST - 1; t++) {
        load_tileA(t, t);
        asm volatile("cp.async.commit_group;");
    }

    // ================= Phase 1: 24 x k32, [agg|X] @ W1 =================
    for (int t32 = 0; t32 < NP1; t32++) {
        // B for both k16 halves: one coalesced LDG.128 per nt
        uint4 bfr[8];
        #pragma unroll
        for (int nt = 0; nt < 8; nt++)
            bfr[nt] = w1q[(((size_t)(wn * 8 + nt) * NP1 + t32) * 32) + lane];

        asm volatile("cp.async.wait_group %0;" :: "n"(NST - 2));
        __syncthreads();
        const int st = t32 & (NST - 1);
        {
            const int tn = t32 + NST - 1;
            if (tn < NP1) load_tileA(tn & (NST - 1), tn);
            asm volatile("cp.async.commit_group;");
        }
        const uint32_t* Aw = Asw + st * (A_STG_B / 4);

        #pragma unroll
        for (int ks = 0; ks < 2; ks++) {
            const int kw = ks * 8;
            uint32_t a[2][4];
            #pragma unroll
            for (int mt = 0; mt < 2; mt++) {
                const int r = wm * 32 + mt * 16 + g;
                a[mt][0] = Aw[(r    ) * 20 + kw + tg    ];
                a[mt][1] = Aw[(r + 8) * 20 + kw + tg    ];
                a[mt][2] = Aw[(r    ) * 20 + kw + tg + 4];
                a[mt][3] = Aw[(r + 8) * 20 + kw + tg + 4];
            }
            #pragma unroll
            for (int mt = 0; mt < 2; mt++)
                #pragma unroll
                for (int nt = 0; nt < 8; nt++)
                    mma_f16(acc[mt][nt], a[mt][0], a[mt][1], a[mt][2], a[mt][3],
                            ks ? bfr[nt].z : bfr[nt].x,
                            ks ? bfr[nt].w : bfr[nt].y);
        }
    }

    // ---- epilogue 1: bias + tanh -> Cs fp16 ----
    __syncthreads();
    #pragma unroll
    for (int mt = 0; mt < 2; mt++) {
        const int r0 = wm * 32 + mt * 16 + g;
        #pragma unroll
        for (int nt = 0; nt < 8; nt++) {
            const int col = wn * 64 + nt * 8 + tg * 2;
            const float bb0 = b1[col];
            const float bb1 = b1[col + 1];
            Csw[(r0    ) * 140 + (col >> 1)] =
                pack_h2(tanh_approx(acc[mt][nt][0] + bb0),
                        tanh_approx(acc[mt][nt][1] + bb1));
            Csw[(r0 + 8) * 140 + (col >> 1)] =
                pack_h2(tanh_approx(acc[mt][nt][2] + bb0),
                        tanh_approx(acc[mt][nt][3] + bb1));
            acc[mt][nt][0] = 0.f; acc[mt][nt][1] = 0.f;
            acc[mt][nt][2] = 0.f; acc[mt][nt][3] = 0.f;
        }
    }
    __syncthreads();

    // ================= Phase 2: 8 x k32, Cs @ W2 =================
    for (int p = 0; p < NP2; p++) {
        uint4 bfr[8];
        #pragma unroll
        for (int nt = 0; nt < 8; nt++)
            bfr[nt] = w2q[(((size_t)(wn * 8 + nt) * NP2 + p) * 32) + lane];

        #pragma unroll
        for (int ks = 0; ks < 2; ks++) {
            const int kw = (2 * p + ks) * 8;
            uint32_t a[2][4];
            #pragma unroll
            for (int mt = 0; mt < 2; mt++) {
                const int r = wm * 32 + mt * 16 + g;
                a[mt][0] = Csw[(r    ) * 140 + kw + tg    ];
                a[mt][1] = Csw[(r + 8) * 140 + kw + tg    ];
                a[mt][2] = Csw[(r    ) * 140 + kw + tg + 4];
                a[mt][3] = Csw[(r + 8) * 140 + kw + tg + 4];
            }
            #pragma unroll
            for (int mt = 0; mt < 2; mt++)
                #pragma unroll
                for (int nt = 0; nt < 8; nt++)
                    mma_f16(acc[mt][nt], a[mt][0], a[mt][1], a[mt][2], a[mt][3],
                            ks ? bfr[nt].z : bfr[nt].x,
                            ks ? bfr[nt].w : bfr[nt].y);
        }
    }

    // ---- epilogue 2: bias + tanh -> global fp32 ----
    #pragma unroll
    for (int mt = 0; mt < 2; mt++) {
        const int r0 = rowBase + wm * 32 + mt * 16 + g;
        #pragma unroll
        for (int nt = 0; nt < 8; nt++) {
            const int col = wn * 64 + nt * 8 + tg * 2;
            const float bb0 = b2[col];
            const float bb1 = b2[col + 1];
            if (r0 < rows) {
                float2 v;
                v.x = tanh_approx(acc[mt][nt][0] + bb0);
                v.y = tanh_approx(acc[mt][nt][1] + bb1);
                *reinterpret_cast<float2*>(Out + (size_t)r0 * 256 + col) = v;
            }
            if (r0 + 8 < rows) {
                float2 v;
                v.x = tanh_approx(acc[mt][nt][2] + bb0);
                v.y = tanh_approx(acc[mt][nt][3] + bb1);
                *reinterpret_cast<float2*>(Out + (size_t)(r0 + 8) * 256 + col) = v;
            }
        }
    }
}

// ---------------------------------------------------------------------------
// Launcher. Inputs (metadata order): X, e, ri_idx, ro_idx, W1, b1, W2, b2
// ---------------------------------------------------------------------------
extern "C" void kernel_launch(void* const* d_in, const int* in_sizes, int n_in,
                              void* d_out, int out_size)
{
    (void)in_sizes; (void)n_in; (void)out_size;

    const float* X  = (const float*)d_in[0];
    const float* e  = (const float*)d_in[1];
    const int*   ri = (const int*)  d_in[2];
    const int*   ro = (const int*)  d_in[3];
    const float* W1 = (const float*)d_in[4];
    const float* b1 = (const float*)d_in[5];
    const float* W2 = (const float*)d_in[6];
    const float* b2 = (const float*)d_in[7];
    float* out = (float*)d_out;

    __half *w1p_ptr = nullptr, *w2p_ptr = nullptr;
    cudaGetSymbolAddress((void**)&w1p_ptr, g_w1p);
    cudaGetSymbolAddress((void**)&w2p_ptr, g_w2p);

    cudaFuncSetAttribute(fused_mlp_kernel,
                         cudaFuncAttributeMaxDynamicSharedMemorySize, SMEM_BYTES);

    // 1: convx+count, 2: scan, 3: fill, 4: gather (profiled)
    convx_count_kernel<<<(BB * EE + 255) / 256, 256>>>(X, ri, ro);
    scan_kernel<<<SCAN_NB, 256>>>();
    fill_kernel<<<(BB * EE + 255) / 256, 256>>>(e, ri, ro);
    gather_kernel<<<(SEG / 2) / 8, 256>>>();

    // 5/6: weight fragment packing
    convw_pack_kernel<<<(32 * NT1 * 32 + 255) / 256, 256>>>(W1, w1p_ptr, KTOT, 256);
    convw_pack_kernel<<<(32 * NT2 * 32 + 255) / 256, 256>>>(W2, w2p_ptr, 256, 256);

    // 7: fused MLP
    const int nblk = (RR + GBM - 1) / GBM;    // 782
    fused_mlp_kernel<<<nblk, 512, SMEM_BYTES>>>(b1, b2, out, RR);
}

// round 16
// speedup vs baseline: 1.9842x; 1.0392x over previous
#include <cuda_runtime.h>
#include <cuda_fp16.h>
#include <cstdint>
#include <cstddef>

// Problem constants (fixed by the reference)
#define BB   2
#define NN   50000
#define EE   150000
#define FF   256
#define OUTD 256
#define RR   (BB * NN)       // 100000 rows
#define KTOT (3 * FF)        // 768
#define SEG  (4 * NN)        // 200000 segments
#define TOTE (4 * EE)        // 600000 CSR entries

#define NT1 48               // k16 bricks for W1
#define NT2 16               // k16 bricks for W2
#define NP1 (NT1 / 2)        // 24 k32 chunks (W1)
#define NP2 (NT2 / 2)        // 8  k32 chunks (W2)
#define NC1 12               // k64 chunks (phase 1)

// fp16 operand buffers
__device__ __half g_agg_h[(size_t)RR * 512];   // [r][0:256]=mi, [r][256:512]=mo
__device__ __half g_x_h[(size_t)RR * 256];     // X in fp16
// Fragment-packed weights, layout [nb][t32][lane][2 bricks of 4 halves]:
// (nb,t32) group = 32 lanes x 16B contiguous (coalesced LDG.128).
__device__ __half g_w1p[32 * NT1 * 128];
__device__ __half g_w2p[32 * NT2 * 128];

// CSR scratch (self-cleaning across calls)
__device__ int   g_count[SEG];
__device__ int   g_fill[SEG];
__device__ int   g_start[SEG];
__device__ int2  g_entry[TOTE];                // .x = src node, .y = weight bits

#define SCAN_TILE 2048
#define SCAN_NB   ((SEG + SCAN_TILE - 1) / SCAN_TILE)   // 98
__device__ volatile int g_scan_state[SCAN_NB];
__device__ int g_scan_agg[SCAN_NB];
__device__ int g_scan_incl[SCAN_NB];

// ---------------------------------------------------------------------------
// helpers
// ---------------------------------------------------------------------------
__device__ __forceinline__ float tanh_approx(float x) {
    float y;
    asm("tanh.approx.f32 %0, %1;" : "=f"(y) : "f"(x));
    return y;
}
__device__ __forceinline__ void cp16(uint32_t dst, const void* src, int bytes) {
    asm volatile("cp.async.cg.shared.global [%0], [%1], 16, %2;"
                 :: "r"(dst), "l"(src), "r"(bytes));
}
__device__ __forceinline__ uint32_t pack_h2(float lo, float hi) {
    __half2 h = __floats2half2_rn(lo, hi);
    return *reinterpret_cast<uint32_t*>(&h);
}
__device__ __forceinline__ void mma_f16(float c[4],
                                        uint32_t a0, uint32_t a1, uint32_t a2, uint32_t a3,
                                        uint32_t b0, uint32_t b1) {
    asm volatile(
        "mma.sync.aligned.m16n8k16.row.col.f32.f16.f16.f32 "
        "{%0,%1,%2,%3}, {%4,%5,%6,%7}, {%8,%9}, {%0,%1,%2,%3};"
        : "+f"(c[0]), "+f"(c[1]), "+f"(c[2]), "+f"(c[3])
        : "r"(a0), "r"(a1), "r"(a2), "r"(a3), "r"(b0), "r"(b1));
}

// ---------------------------------------------------------------------------
// 1) convx + count fused
// ---------------------------------------------------------------------------
__global__ void __launch_bounds__(256) convx_count_kernel(
    const float* __restrict__ X,
    const int* __restrict__ ri_idx,
    const int* __restrict__ ro_idx)
{
    const int t = blockIdx.x * blockDim.x + threadIdx.x;
    if (t < BB * EE) {
        int b = t / EE;
        atomicAdd(&g_count[(2 * b + 0) * NN + ri_idx[t]], 1);
        atomicAdd(&g_count[(2 * b + 1) * NN + ro_idx[t]], 1);
    }
    const size_t total = (size_t)RR * 256 / 8;
    uint4* dst = reinterpret_cast<uint4*>(g_x_h);
    const float4* src = reinterpret_cast<const float4*>(X);
    for (size_t i = (size_t)blockIdx.x * blockDim.x + threadIdx.x;
         i < total; i += (size_t)gridDim.x * blockDim.x) {
        float4 f0 = src[2 * i];
        float4 f1 = src[2 * i + 1];
        uint4 o;
        o.x = pack_h2(f0.x, f0.y); o.y = pack_h2(f0.z, f0.w);
        o.z = pack_h2(f1.x, f1.y); o.w = pack_h2(f1.z, f1.w);
        dst[i] = o;
    }
}

// ---------------------------------------------------------------------------
// 2) scan: decoupled lookback; re-zeros g_count
// ---------------------------------------------------------------------------
__global__ void __launch_bounds__(256) scan_kernel() {
    __shared__ int sh[256];
    __shared__ int s_off;
    const int bid = blockIdx.x;
    const int base = bid * SCAN_TILE + threadIdx.x * 8;

    int v[8]; int s = 0;
    #pragma unroll
    for (int j = 0; j < 8; j++) {
        int idx = base + j;
        int x = 0;
        if (idx < SEG) { x = g_count[idx]; g_count[idx] = 0; }
        v[j] = s;
        s += x;
    }
    sh[threadIdx.x] = s;
    __syncthreads();
    int acc = s;
    #pragma unroll
    for (int off = 1; off < 256; off <<= 1) {
        int t = (threadIdx.x >= off) ? sh[threadIdx.x - off] : 0;
        __syncthreads();
        acc += t;
        sh[threadIdx.x] = acc;
        __syncthreads();
    }
    const int excl_thread = acc - s;

    if (threadIdx.x == 255) {
        if (bid == 0) {
            g_scan_incl[0] = acc;
            __threadfence();
            g_scan_state[0] = 2;
            s_off = 0;
        } else {
            g_scan_agg[bid] = acc;
            __threadfence();
            g_scan_state[bid] = 1;
        }
    }
    if (bid > 0 && threadIdx.x == 0) {
        int off = 0;
        int j = bid - 1;
        while (true) {
            int st;
            do { st = g_scan_state[j]; } while (st == 0);
            __threadfence();
            if (st == 2) { off += g_scan_incl[j]; break; }
            off += g_scan_agg[j];
            j--;
        }
        s_off = off;
    }
    __syncthreads();
    const int off = s_off;
    if (bid > 0 && threadIdx.x == 255) {
        g_scan_incl[bid] = off + acc;
        __threadfence();
        g_scan_state[bid] = 2;
    }
    #pragma unroll
    for (int j = 0; j < 8; j++) {
        int idx = base + j;
        if (idx < SEG) g_start[idx] = off + excl_thread + v[j];
    }
}

// ---------------------------------------------------------------------------
// 3) fill CSR; resets scan flags
// ---------------------------------------------------------------------------
__global__ void fill_kernel(const float* __restrict__ e,
                            const int* __restrict__ ri_idx,
                            const int* __restrict__ ro_idx) {
    int t = blockIdx.x * blockDim.x + threadIdx.x;
    if (t < SCAN_NB) g_scan_state[t] = 0;
    if (t >= BB * EE) return;
    int b = t / EE;
    float w = e[t];
    int ri = ri_idx[t];
    int ro = ro_idx[t];
    int s0 = (2 * b + 0) * NN + ri;
    int s1 = (2 * b + 1) * NN + ro;
    int p0 = g_start[s0] + atomicAdd(&g_fill[s0], 1);
    g_entry[p0] = make_int2(ro, __float_as_int(w));
    int p1 = g_start[s1] + atomicAdd(&g_fill[s1], 1);
    g_entry[p1] = make_int2(ri, __float_as_int(w));
}

// ---------------------------------------------------------------------------
// 4) gather on fp16 X: one warp, two adjacent segments (contiguous CSR).
// ALL entries (cT = cA+cB <= 32 w.h.p.) preloaded with ONE coalesced lane
// load + shfl.idx broadcast -> row-load address is shfl-latency away, not an
// L2 round-trip. Row chains stay independent unroll-2 (4 row-loads in flight).
// Warp-uniform memory fallback for the (astronomically rare) cT > 32.
// ---------------------------------------------------------------------------
__device__ __forceinline__ void fma8(float a[8], float w, const uint4& r) {
    const __half2* h = reinterpret_cast<const __half2*>(&r);
    #pragma unroll
    for (int i = 0; i < 4; i++) {
        float2 f = __half22float2(h[i]);
        a[2 * i]     = fmaf(w, f.x, a[2 * i]);
        a[2 * i + 1] = fmaf(w, f.y, a[2 * i + 1]);
    }
}

__global__ void __launch_bounds__(256) gather_kernel() {
    int wt = blockIdx.x * 8 + (threadIdx.x >> 5);
    if (wt >= SEG / 2) return;
    int lane = threadIdx.x & 31;
    const int segA = wt * 2;                  // pair shares arr (NN even)

    const int arr = segA / NN;
    const int n0  = segA - arr * NN;
    const int b   = arr >> 1;
    const int dir = arr & 1;

    const int sA = g_start[segA];
    int c = 0;
    if (lane < 2) { c = g_fill[segA + lane]; g_fill[segA + lane] = 0; }
    const int cA = __shfl_sync(0xffffffffu, c, 0);
    const int cB = __shfl_sync(0xffffffffu, c, 1);
    const int cT = cA + cB;

    // one coalesced entry preload for the whole pair
    int2 ev = make_int2(0, 0);
    if (lane < cT) ev = g_entry[sA + lane];

    const uint4* Xb = reinterpret_cast<const uint4*>(g_x_h + (size_t)b * NN * FF);
    float aA[8] = {0.f, 0.f, 0.f, 0.f, 0.f, 0.f, 0.f, 0.f};
    float aB[8] = {0.f, 0.f, 0.f, 0.f, 0.f, 0.f, 0.f, 0.f};
    const uint4 z4 = make_uint4(0, 0, 0, 0);

    // j is warp-uniform; p is warp-uniform
    auto getE = [&](int j, bool p) -> int2 {
        int2 r;
        r.x = __shfl_sync(0xffffffffu, ev.x, j & 31);
        r.y = __shfl_sync(0xffffffffu, ev.y, j & 31);
        if (p && j >= 32) r = g_entry[sA + j];   // rare uniform fallback
        return r;
    };

    int iA = 0, iB = 0;
    while (iA < cA || iB < cB) {
        const bool pA0 = iA < cA,     pA1 = iA + 1 < cA;
        const bool pB0 = iB < cB,     pB1 = iB + 1 < cB;
        int2 eA0 = getE(iA,          pA0);
        int2 eA1 = getE(iA + 1,      pA1);
        int2 eB0 = getE(cA + iB,     pB0);
        int2 eB1 = getE(cA + iB + 1, pB1);

        uint4 rA0 = z4, rA1 = z4, rB0 = z4, rB1 = z4;
        if (pA0) rA0 = Xb[(size_t)eA0.x * 32 + lane];
        if (pA1) rA1 = Xb[(size_t)eA1.x * 32 + lane];
        if (pB0) rB0 = Xb[(size_t)eB0.x * 32 + lane];
        if (pB1) rB1 = Xb[(size_t)eB1.x * 32 + lane];

        fma8(aA, pA0 ? __int_as_float(eA0.y) : 0.f, rA0);
        fma8(aA, pA1 ? __int_as_float(eA1.y) : 0.f, rA1);
        fma8(aB, pB0 ? __int_as_float(eB0.y) : 0.f, rB0);
        fma8(aB, pB1 ? __int_as_float(eB1.y) : 0.f, rB1);
        iA += 2; iB += 2;
    }

    uint4 oA, oB;
    oA.x = pack_h2(aA[0], aA[1]); oA.y = pack_h2(aA[2], aA[3]);
    oA.z = pack_h2(aA[4], aA[5]); oA.w = pack_h2(aA[6], aA[7]);
    oB.x = pack_h2(aB[0], aB[1]); oB.y = pack_h2(aB[2], aB[3]);
    oB.z = pack_h2(aB[4], aB[5]); oB.w = pack_h2(aB[6], aB[7]);

    __half* dA = g_agg_h + ((size_t)b * NN + n0    ) * 512 + dir * 256;
    __half* dB = g_agg_h + ((size_t)b * NN + n0 + 1) * 512 + dir * 256;
    *reinterpret_cast<uint4*>(dA + 8 * lane) = oA;
    *reinterpret_cast<uint4*>(dB + 8 * lane) = oB;
}

// ---------------------------------------------------------------------------
// 5/6) pack W[K][N] fp32 -> fragment bricks fp16, layout [nb][t32][lane][pair]
// ---------------------------------------------------------------------------
__global__ void convw_pack_kernel(const float* __restrict__ W, __half* __restrict__ out,
                                  int K, int N) {
    int idx = blockIdx.x * blockDim.x + threadIdx.x;
    int nkb = K / 16;
    int total = (N / 8) * nkb * 32;
    if (idx >= total) return;
    int lane = idx & 31;
    int brick = idx >> 5;
    int nb = brick / nkb;
    int kb = brick - nb * nkb;
    int g = lane >> 2, tg = lane & 3;
    int n = nb * 8 + g;
    int k0 = kb * 16 + 2 * tg;
    __half h[4];
    h[0] = __float2half_rn(W[(size_t)(k0    ) * N + n]);
    h[1] = __float2half_rn(W[(size_t)(k0 + 1) * N + n]);
    h[2] = __float2half_rn(W[(size_t)(k0 + 8) * N + n]);
    h[3] = __float2half_rn(W[(size_t)(k0 + 9) * N + n]);
    size_t o = (((size_t)nb * (nkb / 2) + (kb >> 1)) * 32 + lane) * 8 + (kb & 1) * 4;
    *reinterpret_cast<uint2*>(out + o) = *reinterpret_cast<uint2*>(h);
}

// ---------------------------------------------------------------------------
// 7) Fused 2-layer MLP, fp16 m16n8k16, 512 threads, K-chunk 64 (phase 1).
// A: 4-stage cp.async ring (stage = 128 rows x 72 halves = 18432 B; word
//    stride 36 -> frag banks 4g+tg distinct). 12 barrier rounds (was 24).
// B: coalesced LDG.128 per (warp, nt) per k32 half; second half's B loaded
//    mid-iteration into the SAME registers (no pressure growth).
// ---------------------------------------------------------------------------
#define GBM 128
#define NST 4
#define A_LDH 72
#define C_LDH 280
#define A_STG_B (GBM * A_LDH * 2)                 // 18432 B
#define CS_OFF  (NST * A_STG_B)                   // 73728
#define SMEM_BYTES (CS_OFF + GBM * C_LDH * 2)     // 145408

__global__ void __launch_bounds__(512, 1) fused_mlp_kernel(
    const float* __restrict__ b1,
    const float* __restrict__ b2,
    float* __restrict__ Out,
    int rows)
{
    extern __shared__ char smem[];
    const uint32_t smem_u = (uint32_t)__cvta_generic_to_shared(smem);
    const uint32_t* Asw = reinterpret_cast<const uint32_t*>(smem);
    uint32_t* Csw = reinterpret_cast<uint32_t*>(smem + CS_OFF);

    const int tid  = threadIdx.x;
    const int warp = tid >> 5;
    const int lane = tid & 31;
    const int g    = lane >> 2;
    const int tg   = lane & 3;
    const int wm   = warp & 3;         // M group (32 rows)
    const int wn   = warp >> 2;        // N group (64 cols)
    const int rowBase = blockIdx.x * GBM;

    const uint4* w1q = reinterpret_cast<const uint4*>(g_w1p);
    const uint4* w2q = reinterpret_cast<const uint4*>(g_w2p);

    float acc[2][8][4];
    #pragma unroll
    for (int mt = 0; mt < 2; mt++)
        #pragma unroll
        for (int nt = 0; nt < 8; nt++)
            #pragma unroll
            for (int r = 0; r < 4; r++) acc[mt][nt][r] = 0.f;

    // A loader: k64 tile = 128 rows x 64 halves = 1024 x 16B -> 2 per thread
    auto load_tileA = [&](int st, int t64) {
        const int k0 = t64 * 64;
        const int row = tid >> 2;
        const int kcq = (tid & 3) * 8;
        const int gr  = rowBase + row;
        #pragma unroll
        for (int h = 0; h < 2; h++) {
            const int kc = kcq + h * 32;
            const int kk = k0 + kc;
            const __half* asrc = (kk < 512)
                ? g_agg_h + (size_t)gr * 512 + kk
                : g_x_h   + (size_t)gr * 256 + (kk - 512);
            cp16(smem_u + (uint32_t)(st * A_STG_B + (row * A_LDH + kc) * 2),
                 asrc, gr < rows ? 16 : 0);
        }
    };

    #pragma unroll
    for (int t = 0; t < NST - 1; t++) {
        load_tileA(t, t);
        asm volatile("cp.async.commit_group;");
    }

    // ================= Phase 1: 12 x k64, [agg|X] @ W1 =================
    for (int t = 0; t < NC1; t++) {
        // B for the first k32 half (t32 = 2t)
        uint4 bfr[8];
        #pragma unroll
        for (int nt = 0; nt < 8; nt++)
            bfr[nt] = w1q[(((size_t)(wn * 8 + nt) * NP1 + 2 * t) * 32) + lane];

        asm volatile("cp.async.wait_group %0;" :: "n"(NST - 2));
        __syncthreads();
        const int st = t & (NST - 1);
        {
            const int tn = t + NST - 1;
            if (tn < NC1) load_tileA(tn & (NST - 1), tn);
            asm volatile("cp.async.commit_group;");
        }
        const uint32_t* Aw = Asw + st * (A_STG_B / 4);

        #pragma unroll
        for (int half = 0; half < 2; half++) {
            #pragma unroll
            for (int ks = 0; ks < 2; ks++) {
                const int kw = (half * 2 + ks) * 8;    // word offset in A row
                uint32_t a[2][4];
                #pragma unroll
                for (int mt = 0; mt < 2; mt++) {
                    const int r = wm * 32 + mt * 16 + g;
                    a[mt][0] = Aw[(r    ) * 36 + kw + tg    ];
                    a[mt][1] = Aw[(r + 8) * 36 + kw + tg    ];
                    a[mt][2] = Aw[(r    ) * 36 + kw + tg + 4];
                    a[mt][3] = Aw[(r + 8) * 36 + kw + tg + 4];
                }
                #pragma unroll
                for (int mt = 0; mt < 2; mt++)
                    #pragma unroll
                    for (int nt = 0; nt < 8; nt++)
                        mma_f16(acc[mt][nt], a[mt][0], a[mt][1], a[mt][2], a[mt][3],
                                ks ? bfr[nt].z : bfr[nt].x,
                                ks ? bfr[nt].w : bfr[nt].y);
            }
            // load B for the second half (t32 = 2t+1) into the same regs
            if (half == 0) {
                #pragma unroll
                for (int nt = 0; nt < 8; nt++)
                    bfr[nt] = w1q[(((size_t)(wn * 8 + nt) * NP1 + 2 * t + 1) * 32) + lane];
            }
        }
    }

    // ---- epilogue 1: bias + tanh -> Cs fp16 ----
    __syncthreads();
    #pragma unroll
    for (int mt = 0; mt < 2; mt++) {
        const int r0 = wm * 32 + mt * 16 + g;
        #pragma unroll
        for (int nt = 0; nt < 8; nt++) {
            const int col = wn * 64 + nt * 8 + tg * 2;
            const float bb0 = b1[col];
            const float bb1 = b1[col + 1];
            Csw[(r0    ) * 140 + (col >> 1)] =
                pack_h2(tanh_approx(acc[mt][nt][0] + bb0),
                        tanh_approx(acc[mt][nt][1] + bb1));
            Csw[(r0 + 8) * 140 + (col >> 1)] =
                pack_h2(tanh_approx(acc[mt][nt][2] + bb0),
                        tanh_approx(acc[mt][nt][3] + bb1));
            acc[mt][nt][0] = 0.f; acc[mt][nt][1] = 0.f;
            acc[mt][nt][2] = 0.f; acc[mt][nt][3] = 0.f;
        }
    }
    __syncthreads();

    // ================= Phase 2: 8 x k32, Cs @ W2 =================
    for (int p = 0; p < NP2; p++) {
        uint4 bfr[8];
        #pragma unroll
        for (int nt = 0; nt < 8; nt++)
            bfr[nt] = w2q[(((size_t)(wn * 8 + nt) * NP2 + p) * 32) + lane];

        #pragma unroll
        for (int ks = 0; ks < 2; ks++) {
            const int kw = (2 * p + ks) * 8;
            uint32_t a[2][4];
            #pragma unroll
            for (int mt = 0; mt < 2; mt++) {
                const int r = wm * 32 + mt * 16 + g;
                a[mt][0] = Csw[(r    ) * 140 + kw + tg    ];
                a[mt][1] = Csw[(r + 8) * 140 + kw + tg    ];
                a[mt][2] = Csw[(r    ) * 140 + kw + tg + 4];
                a[mt][3] = Csw[(r + 8) * 140 + kw + tg + 4];
            }
            #pragma unroll
            for (int mt = 0; mt < 2; mt++)
                #pragma unroll
                for (int nt = 0; nt < 8; nt++)
                    mma_f16(acc[mt][nt], a[mt][0], a[mt][1], a[mt][2], a[mt][3],
                            ks ? bfr[nt].z : bfr[nt].x,
                            ks ? bfr[nt].w : bfr[nt].y);
        }
    }

    // ---- epilogue 2: bias + tanh -> global fp32 ----
    #pragma unroll
    for (int mt = 0; mt < 2; mt++) {
        const int r0 = rowBase + wm * 32 + mt * 16 + g;
        #pragma unroll
        for (int nt = 0; nt < 8; nt++) {
            const int col = wn * 64 + nt * 8 + tg * 2;
            const float bb0 = b2[col];
            const float bb1 = b2[col + 1];
            if (r0 < rows) {
                float2 v;
                v.x = tanh_approx(acc[mt][nt][0] + bb0);
                v.y = tanh_approx(acc[mt][nt][1] + bb1);
                *reinterpret_cast<float2*>(Out + (size_t)r0 * 256 + col) = v;
            }
            if (r0 + 8 < rows) {
                float2 v;
                v.x = tanh_approx(acc[mt][nt][2] + bb0);
                v.y = tanh_approx(acc[mt][nt][3] + bb1);
                *reinterpret_cast<float2*>(Out + (size_t)(r0 + 8) * 256 + col) = v;
            }
        }
    }
}

// ---------------------------------------------------------------------------
// Launcher. Inputs (metadata order): X, e, ri_idx, ro_idx, W1, b1, W2, b2
// ---------------------------------------------------------------------------
extern "C" void kernel_launch(void* const* d_in, const int* in_sizes, int n_in,
                              void* d_out, int out_size)
{
    (void)in_sizes; (void)n_in; (void)out_size;

    const float* X  = (const float*)d_in[0];
    const float* e  = (const float*)d_in[1];
    const int*   ri = (const int*)  d_in[2];
    const int*   ro = (const int*)  d_in[3];
    const float* W1 = (const float*)d_in[4];
    const float* b1 = (const float*)d_in[5];
    const float* W2 = (const float*)d_in[6];
    const float* b2 = (const float*)d_in[7];
    float* out = (float*)d_out;

    __half *w1p_ptr = nullptr, *w2p_ptr = nullptr;
    cudaGetSymbolAddress((void**)&w1p_ptr, g_w1p);
    cudaGetSymbolAddress((void**)&w2p_ptr, g_w2p);

    cudaFuncSetAttribute(fused_mlp_kernel,
                         cudaFuncAttributeMaxDynamicSharedMemorySize, SMEM_BYTES);

    // 1: convx+count, 2: scan, 3: fill, 4: gather (profiled)
    convx_count_kernel<<<(BB * EE + 255) / 256, 256>>>(X, ri, ro);
    scan_kernel<<<SCAN_NB, 256>>>();
    fill_kernel<<<(BB * EE + 255) / 256, 256>>>(e, ri, ro);
    gather_kernel<<<(SEG / 2) / 8, 256>>>();

    // 5/6: weight fragment packing
    convw_pack_kernel<<<(32 * NT1 * 32 + 255) / 256, 256>>>(W1, w1p_ptr, KTOT, 256);
    convw_pack_kernel<<<(32 * NT2 * 32 + 255) / 256, 256>>>(W2, w2p_ptr, 256, 256);

    // 7: fused MLP
    const int nblk = (RR + GBM - 1) / GBM;    // 782
    fused_mlp_kernel<<<nblk, 512, SMEM_BYTES>>>(b1, b2, out, RR);
}

// round 17
// speedup vs baseline: 2.0576x; 1.0370x over previous
#include <cuda_runtime.h>
#include <cuda_fp16.h>
#include <cstdint>
#include <cstddef>

// Problem constants (fixed by the reference)
#define BB   2
#define NN   50000
#define EE   150000
#define FF   256
#define OUTD 256
#define RR   (BB * NN)       // 100000 rows
#define KTOT (3 * FF)        // 768
#define SEG  (4 * NN)        // 200000 segments
#define TOTE (4 * EE)        // 600000 CSR entries

#define NT1 48               // k16 bricks for W1
#define NT2 16               // k16 bricks for W2
#define NP1 (NT1 / 2)        // 24 k32 chunks (W1)
#define NP2 (NT2 / 2)        // 8  k32 chunks (W2)
#define NC1 12               // k64 chunks (phase 1)

// fp16 operand buffers
__device__ __half g_agg_h[(size_t)RR * 512];   // [r][0:256]=mi, [r][256:512]=mo
__device__ __half g_x_h[(size_t)RR * 256];     // X in fp16
// Fragment-packed weights, layout [nb][t32][lane][2 bricks of 4 halves]:
// (nb,t32) group = 32 lanes x 16B contiguous (coalesced LDG.128).
__device__ __half g_w1p[32 * NT1 * 128];
__device__ __half g_w2p[32 * NT2 * 128];

// CSR scratch (self-cleaning across calls)
__device__ int   g_count[SEG];
__device__ int   g_fill[SEG];
__device__ int   g_start[SEG];
__device__ int2  g_entry[TOTE];                // .x = src node, .y = weight bits

#define SCAN_TILE 2048
#define SCAN_NB   ((SEG + SCAN_TILE - 1) / SCAN_TILE)   // 98
__device__ volatile int g_scan_state[SCAN_NB];
__device__ int g_scan_agg[SCAN_NB];
__device__ int g_scan_incl[SCAN_NB];

// ---------------------------------------------------------------------------
// helpers
// ---------------------------------------------------------------------------
__device__ __forceinline__ float tanh_approx(float x) {
    float y;
    asm("tanh.approx.f32 %0, %1;" : "=f"(y) : "f"(x));
    return y;
}
__device__ __forceinline__ void cp16(uint32_t dst, const void* src, int bytes) {
    asm volatile("cp.async.cg.shared.global [%0], [%1], 16, %2;"
                 :: "r"(dst), "l"(src), "r"(bytes));
}
__device__ __forceinline__ uint32_t pack_h2(float lo, float hi) {
    __half2 h = __floats2half2_rn(lo, hi);
    return *reinterpret_cast<uint32_t*>(&h);
}
__device__ __forceinline__ void mma_f16(float c[4],
                                        uint32_t a0, uint32_t a1, uint32_t a2, uint32_t a3,
                                        uint32_t b0, uint32_t b1) {
    asm volatile(
        "mma.sync.aligned.m16n8k16.row.col.f32.f16.f16.f32 "
        "{%0,%1,%2,%3}, {%4,%5,%6,%7}, {%8,%9}, {%0,%1,%2,%3};"
        : "+f"(c[0]), "+f"(c[1]), "+f"(c[2]), "+f"(c[3])
        : "r"(a0), "r"(a1), "r"(a2), "r"(a3), "r"(b0), "r"(b1));
}

// ---------------------------------------------------------------------------
// 1) convx + count fused
// ---------------------------------------------------------------------------
__global__ void __launch_bounds__(256) convx_count_kernel(
    const float* __restrict__ X,
    const int* __restrict__ ri_idx,
    const int* __restrict__ ro_idx)
{
    const int t = blockIdx.x * blockDim.x + threadIdx.x;
    if (t < BB * EE) {
        int b = t / EE;
        atomicAdd(&g_count[(2 * b + 0) * NN + ri_idx[t]], 1);
        atomicAdd(&g_count[(2 * b + 1) * NN + ro_idx[t]], 1);
    }
    const size_t total = (size_t)RR * 256 / 8;
    uint4* dst = reinterpret_cast<uint4*>(g_x_h);
    const float4* src = reinterpret_cast<const float4*>(X);
    for (size_t i = (size_t)blockIdx.x * blockDim.x + threadIdx.x;
         i < total; i += (size_t)gridDim.x * blockDim.x) {
        float4 f0 = src[2 * i];
        float4 f1 = src[2 * i + 1];
        uint4 o;
        o.x = pack_h2(f0.x, f0.y); o.y = pack_h2(f0.z, f0.w);
        o.z = pack_h2(f1.x, f1.y); o.w = pack_h2(f1.z, f1.w);
        dst[i] = o;
    }
}

// ---------------------------------------------------------------------------
// 2) scan: decoupled lookback; re-zeros g_count
// ---------------------------------------------------------------------------
__global__ void __launch_bounds__(256) scan_kernel() {
    __shared__ int sh[256];
    __shared__ int s_off;
    const int bid = blockIdx.x;
    const int base = bid * SCAN_TILE + threadIdx.x * 8;

    int v[8]; int s = 0;
    #pragma unroll
    for (int j = 0; j < 8; j++) {
        int idx = base + j;
        int x = 0;
        if (idx < SEG) { x = g_count[idx]; g_count[idx] = 0; }
        v[j] = s;
        s += x;
    }
    sh[threadIdx.x] = s;
    __syncthreads();
    int acc = s;
    #pragma unroll
    for (int off = 1; off < 256; off <<= 1) {
        int t = (threadIdx.x >= off) ? sh[threadIdx.x - off] : 0;
        __syncthreads();
        acc += t;
        sh[threadIdx.x] = acc;
        __syncthreads();
    }
    const int excl_thread = acc - s;

    if (threadIdx.x == 255) {
        if (bid == 0) {
            g_scan_incl[0] = acc;
            __threadfence();
            g_scan_state[0] = 2;
            s_off = 0;
        } else {
            g_scan_agg[bid] = acc;
            __threadfence();
            g_scan_state[bid] = 1;
        }
    }
    if (bid > 0 && threadIdx.x == 0) {
        int off = 0;
        int j = bid - 1;
        while (true) {
            int st;
            do { st = g_scan_state[j]; } while (st == 0);
            __threadfence();
            if (st == 2) { off += g_scan_incl[j]; break; }
            off += g_scan_agg[j];
            j--;
        }
        s_off = off;
    }
    __syncthreads();
    const int off = s_off;
    if (bid > 0 && threadIdx.x == 255) {
        g_scan_incl[bid] = off + acc;
        __threadfence();
        g_scan_state[bid] = 2;
    }
    #pragma unroll
    for (int j = 0; j < 8; j++) {
        int idx = base + j;
        if (idx < SEG) g_start[idx] = off + excl_thread + v[j];
    }
}

// ---------------------------------------------------------------------------
// 3) fill CSR; resets scan flags
// ---------------------------------------------------------------------------
__global__ void fill_kernel(const float* __restrict__ e,
                            const int* __restrict__ ri_idx,
                            const int* __restrict__ ro_idx) {
    int t = blockIdx.x * blockDim.x + threadIdx.x;
    if (t < SCAN_NB) g_scan_state[t] = 0;
    if (t >= BB * EE) return;
    int b = t / EE;
    float w = e[t];
    int ri = ri_idx[t];
    int ro = ro_idx[t];
    int s0 = (2 * b + 0) * NN + ri;
    int s1 = (2 * b + 1) * NN + ro;
    int p0 = g_start[s0] + atomicAdd(&g_fill[s0], 1);
    g_entry[p0] = make_int2(ro, __float_as_int(w));
    int p1 = g_start[s1] + atomicAdd(&g_fill[s1], 1);
    g_entry[p1] = make_int2(ri, __float_as_int(w));
}

// ---------------------------------------------------------------------------
// 4) gather on fp16 X (R10/R15 version — measured best at ~98us):
// one warp, two segments, independent unroll-2 chains (4 row-loads in flight).
// ---------------------------------------------------------------------------
__device__ __forceinline__ void fma8(float a[8], float w, const uint4& r) {
    const __half2* h = reinterpret_cast<const __half2*>(&r);
    #pragma unroll
    for (int i = 0; i < 4; i++) {
        float2 f = __half22float2(h[i]);
        a[2 * i]     = fmaf(w, f.x, a[2 * i]);
        a[2 * i + 1] = fmaf(w, f.y, a[2 * i + 1]);
    }
}

__global__ void __launch_bounds__(256) gather_kernel() {
    int wt = blockIdx.x * 8 + (threadIdx.x >> 5);
    if (wt >= SEG / 2) return;
    int lane = threadIdx.x & 31;
    int segA = wt * 2;
    int segB = segA + 1;

    int arrA = segA / NN, nA = segA - arrA * NN;
    int arrB = segB / NN, nB = segB - arrB * NN;

    int sA = g_start[segA];
    int sB = g_start[segB];
    int c = 0;
    if (lane < 2) { c = g_fill[segA + lane]; g_fill[segA + lane] = 0; }
    int cA = __shfl_sync(0xffffffffu, c, 0);
    int cB = __shfl_sync(0xffffffffu, c, 1);

    const uint4* XA = reinterpret_cast<const uint4*>(g_x_h + (size_t)(arrA >> 1) * NN * FF);
    const uint4* XB = reinterpret_cast<const uint4*>(g_x_h + (size_t)(arrB >> 1) * NN * FF);

    float aA[8] = {0.f, 0.f, 0.f, 0.f, 0.f, 0.f, 0.f, 0.f};
    float aB[8] = {0.f, 0.f, 0.f, 0.f, 0.f, 0.f, 0.f, 0.f};
    const uint4 z4 = make_uint4(0, 0, 0, 0);

    int iA = sA, eA = sA + cA;
    int iB = sB, eB = sB + cB;
    while (iA < eA || iB < eB) {
        bool pA0 = iA < eA,     pA1 = iA + 1 < eA;
        bool pB0 = iB < eB,     pB1 = iB + 1 < eB;
        int2 eA0 = make_int2(0, 0), eA1 = make_int2(0, 0);
        int2 eB0 = make_int2(0, 0), eB1 = make_int2(0, 0);
        if (pA0) eA0 = g_entry[iA];
        if (pA1) eA1 = g_entry[iA + 1];
        if (pB0) eB0 = g_entry[iB];
        if (pB1) eB1 = g_entry[iB + 1];

        uint4 rA0 = z4, rA1 = z4, rB0 = z4, rB1 = z4;
        if (pA0) rA0 = XA[(size_t)eA0.x * 32 + lane];
        if (pA1) rA1 = XA[(size_t)eA1.x * 32 + lane];
        if (pB0) rB0 = XB[(size_t)eB0.x * 32 + lane];
        if (pB1) rB1 = XB[(size_t)eB1.x * 32 + lane];

        fma8(aA, pA0 ? __int_as_float(eA0.y) : 0.f, rA0);
        fma8(aA, pA1 ? __int_as_float(eA1.y) : 0.f, rA1);
        fma8(aB, pB0 ? __int_as_float(eB0.y) : 0.f, rB0);
        fma8(aB, pB1 ? __int_as_float(eB1.y) : 0.f, rB1);
        iA += 2; iB += 2;
    }

    uint4 oA, oB;
    oA.x = pack_h2(aA[0], aA[1]); oA.y = pack_h2(aA[2], aA[3]);
    oA.z = pack_h2(aA[4], aA[5]); oA.w = pack_h2(aA[6], aA[7]);
    oB.x = pack_h2(aB[0], aB[1]); oB.y = pack_h2(aB[2], aB[3]);
    oB.z = pack_h2(aB[4], aB[5]); oB.w = pack_h2(aB[6], aB[7]);

    __half* dA = g_agg_h + ((size_t)(arrA >> 1) * NN + nA) * 512 + (arrA & 1) * 256;
    __half* dB = g_agg_h + ((size_t)(arrB >> 1) * NN + nB) * 512 + (arrB & 1) * 256;
    *reinterpret_cast<uint4*>(dA + 8 * lane) = oA;
    *reinterpret_cast<uint4*>(dB + 8 * lane) = oB;
}

// ---------------------------------------------------------------------------
// 5/6) pack W[K][N] fp32 -> fragment bricks fp16, layout [nb][t32][lane][pair]
// ---------------------------------------------------------------------------
__global__ void convw_pack_kernel(const float* __restrict__ W, __half* __restrict__ out,
                                  int K, int N) {
    int idx = blockIdx.x * blockDim.x + threadIdx.x;
    int nkb = K / 16;
    int total = (N / 8) * nkb * 32;
    if (idx >= total) return;
    int lane = idx & 31;
    int brick = idx >> 5;
    int nb = brick / nkb;
    int kb = brick - nb * nkb;
    int g = lane >> 2, tg = lane & 3;
    int n = nb * 8 + g;
    int k0 = kb * 16 + 2 * tg;
    __half h[4];
    h[0] = __float2half_rn(W[(size_t)(k0    ) * N + n]);
    h[1] = __float2half_rn(W[(size_t)(k0 + 1) * N + n]);
    h[2] = __float2half_rn(W[(size_t)(k0 + 8) * N + n]);
    h[3] = __float2half_rn(W[(size_t)(k0 + 9) * N + n]);
    size_t o = (((size_t)nb * (nkb / 2) + (kb >> 1)) * 32 + lane) * 8 + (kb & 1) * 4;
    *reinterpret_cast<uint2*>(out + o) = *reinterpret_cast<uint2*>(h);
}

// ---------------------------------------------------------------------------
// 7) Fused 2-layer MLP (R16 version — measured best): fp16 m16n8k16,
// 512 threads, K-chunk 64 phase-1 pipeline (12 barrier rounds), coalesced
// k32 B LDG.128s (second half mid-iteration, same regs).
// A stage = 128 rows x 72 halves (word stride 36 -> frag banks 4g+tg).
// ---------------------------------------------------------------------------
#define GBM 128
#define NST 4
#define A_LDH 72
#define C_LDH 280
#define A_STG_B (GBM * A_LDH * 2)                 // 18432 B
#define CS_OFF  (NST * A_STG_B)                   // 73728
#define SMEM_BYTES (CS_OFF + GBM * C_LDH * 2)     // 145408

__global__ void __launch_bounds__(512, 1) fused_mlp_kernel(
    const float* __restrict__ b1,
    const float* __restrict__ b2,
    float* __restrict__ Out,
    int rows)
{
    extern __shared__ char smem[];
    const uint32_t smem_u = (uint32_t)__cvta_generic_to_shared(smem);
    const uint32_t* Asw = reinterpret_cast<const uint32_t*>(smem);
    uint32_t* Csw = reinterpret_cast<uint32_t*>(smem + CS_OFF);

    const int tid  = threadIdx.x;
    const int warp = tid >> 5;
    const int lane = tid & 31;
    const int g    = lane >> 2;
    const int tg   = lane & 3;
    const int wm   = warp & 3;
    const int wn   = warp >> 2;
    const int rowBase = blockIdx.x * GBM;

    const uint4* w1q = reinterpret_cast<const uint4*>(g_w1p);
    const uint4* w2q = reinterpret_cast<const uint4*>(g_w2p);

    float acc[2][8][4];
    #pragma unroll
    for (int mt = 0; mt < 2; mt++)
        #pragma unroll
        for (int nt = 0; nt < 8; nt++)
            #pragma unroll
            for (int r = 0; r < 4; r++) acc[mt][nt][r] = 0.f;

    auto load_tileA = [&](int st, int t64) {
        const int k0 = t64 * 64;
        const int row = tid >> 2;
        const int kcq = (tid & 3) * 8;
        const int gr  = rowBase + row;
        #pragma unroll
        for (int h = 0; h < 2; h++) {
            const int kc = kcq + h * 32;
            const int kk = k0 + kc;
            const __half* asrc = (kk < 512)
                ? g_agg_h + (size_t)gr * 512 + kk
                : g_x_h   + (size_t)gr * 256 + (kk - 512);
            cp16(smem_u + (uint32_t)(st * A_STG_B + (row * A_LDH + kc) * 2),
                 asrc, gr < rows ? 16 : 0);
        }
    };

    #pragma unroll
    for (int t = 0; t < NST - 1; t++) {
        load_tileA(t, t);
        asm volatile("cp.async.commit_group;");
    }

    // ================= Phase 1: 12 x k64, [agg|X] @ W1 =================
    for (int t = 0; t < NC1; t++) {
        uint4 bfr[8];
        #pragma unroll
        for (int nt = 0; nt < 8; nt++)
            bfr[nt] = w1q[(((size_t)(wn * 8 + nt) * NP1 + 2 * t) * 32) + lane];

        asm volatile("cp.async.wait_group %0;" :: "n"(NST - 2));
        __syncthreads();
        const int st = t & (NST - 1);
        {
            const int tn = t + NST - 1;
            if (tn < NC1) load_tileA(tn & (NST - 1), tn);
            asm volatile("cp.async.commit_group;");
        }
        const uint32_t* Aw = Asw + st * (A_STG_B / 4);

        #pragma unroll
        for (int half = 0; half < 2; half++) {
            #pragma unroll
            for (int ks = 0; ks < 2; ks++) {
                const int kw = (half * 2 + ks) * 8;
                uint32_t a[2][4];
                #pragma unroll
                for (int mt = 0; mt < 2; mt++) {
                    const int r = wm * 32 + mt * 16 + g;
                    a[mt][0] = Aw[(r    ) * 36 + kw + tg    ];
                    a[mt][1] = Aw[(r + 8) * 36 + kw + tg    ];
                    a[mt][2] = Aw[(r    ) * 36 + kw + tg + 4];
                    a[mt][3] = Aw[(r + 8) * 36 + kw + tg + 4];
                }
                #pragma unroll
                for (int mt = 0; mt < 2; mt++)
                    #pragma unroll
                    for (int nt = 0; nt < 8; nt++)
                        mma_f16(acc[mt][nt], a[mt][0], a[mt][1], a[mt][2], a[mt][3],
                                ks ? bfr[nt].z : bfr[nt].x,
                                ks ? bfr[nt].w : bfr[nt].y);
            }
            if (half == 0) {
                #pragma unroll
                for (int nt = 0; nt < 8; nt++)
                    bfr[nt] = w1q[(((size_t)(wn * 8 + nt) * NP1 + 2 * t + 1) * 32) + lane];
            }
        }
    }

    // ---- epilogue 1: bias + tanh -> Cs fp16 ----
    __syncthreads();
    #pragma unroll
    for (int mt = 0; mt < 2; mt++) {
        const int r0 = wm * 32 + mt * 16 + g;
        #pragma unroll
        for (int nt = 0; nt < 8; nt++) {
            const int col = wn * 64 + nt * 8 + tg * 2;
            const float bb0 = b1[col];
            const float bb1 = b1[col + 1];
            Csw[(r0    ) * 140 + (col >> 1)] =
                pack_h2(tanh_approx(acc[mt][nt][0] + bb0),
                        tanh_approx(acc[mt][nt][1] + bb1));
            Csw[(r0 + 8) * 140 + (col >> 1)] =
                pack_h2(tanh_approx(acc[mt][nt][2] + bb0),
                        tanh_approx(acc[mt][nt][3] + bb1));
            acc[mt][nt][0] = 0.f; acc[mt][nt][1] = 0.f;
            acc[mt][nt][2] = 0.f; acc[mt][nt][3] = 0.f;
        }
    }
    __syncthreads();

    // ================= Phase 2: 8 x k32, Cs @ W2 =================
    for (int p = 0; p < NP2; p++) {
        uint4 bfr[8];
        #pragma unroll
        for (int nt = 0; nt < 8; nt++)
            bfr[nt] = w2q[(((size_t)(wn * 8 + nt) * NP2 + p) * 32) + lane];

        #pragma unroll
        for (int ks = 0; ks < 2; ks++) {
            const int kw = (2 * p + ks) * 8;
            uint32_t a[2][4];
            #pragma unroll
            for (int mt = 0; mt < 2; mt++) {
                const int r = wm * 32 + mt * 16 + g;
                a[mt][0] = Csw[(r    ) * 140 + kw + tg    ];
                a[mt][1] = Csw[(r + 8) * 140 + kw + tg    ];
                a[mt][2] = Csw[(r    ) * 140 + kw + tg + 4];
                a[mt][3] = Csw[(r + 8) * 140 + kw + tg + 4];
            }
            #pragma unroll
            for (int mt = 0; mt < 2; mt++)
                #pragma unroll
                for (int nt = 0; nt < 8; nt++)
                    mma_f16(acc[mt][nt], a[mt][0], a[mt][1], a[mt][2], a[mt][3],
                            ks ? bfr[nt].z : bfr[nt].x,
                            ks ? bfr[nt].w : bfr[nt].y);
        }
    }

    // ---- epilogue 2: bias + tanh -> global fp32 ----
    #pragma unroll
    for (int mt = 0; mt < 2; mt++) {
        const int r0 = rowBase + wm * 32 + mt * 16 + g;
        #pragma unroll
        for (int nt = 0; nt < 8; nt++) {
            const int col = wn * 64 + nt * 8 + tg * 2;
            const float bb0 = b2[col];
            const float bb1 = b2[col + 1];
            if (r0 < rows) {
                float2 v;
                v.x = tanh_approx(acc[mt][nt][0] + bb0);
                v.y = tanh_approx(acc[mt][nt][1] + bb1);
                *reinterpret_cast<float2*>(Out + (size_t)r0 * 256 + col) = v;
            }
            if (r0 + 8 < rows) {
                float2 v;
                v.x = tanh_approx(acc[mt][nt][2] + bb0);
                v.y = tanh_approx(acc[mt][nt][3] + bb1);
                *reinterpret_cast<float2*>(Out + (size_t)(r0 + 8) * 256 + col) = v;
            }
        }
    }
}

// ---------------------------------------------------------------------------
// Launcher. Inputs (metadata order): X, e, ri_idx, ro_idx, W1, b1, W2, b2
// ---------------------------------------------------------------------------
extern "C" void kernel_launch(void* const* d_in, const int* in_sizes, int n_in,
                              void* d_out, int out_size)
{
    (void)in_sizes; (void)n_in; (void)out_size;

    const float* X  = (const float*)d_in[0];
    const float* e  = (const float*)d_in[1];
    const int*   ri = (const int*)  d_in[2];
    const int*   ro = (const int*)  d_in[3];
    const float* W1 = (const float*)d_in[4];
    const float* b1 = (const float*)d_in[5];
    const float* W2 = (const float*)d_in[6];
    const float* b2 = (const float*)d_in[7];
    float* out = (float*)d_out;

    __half *w1p_ptr = nullptr, *w2p_ptr = nullptr;
    cudaGetSymbolAddress((void**)&w1p_ptr, g_w1p);
    cudaGetSymbolAddress((void**)&w2p_ptr, g_w2p);

    cudaFuncSetAttribute(fused_mlp_kernel,
                         cudaFuncAttributeMaxDynamicSharedMemorySize, SMEM_BYTES);

    // 1: convx+count, 2: scan, 3: fill, 4: gather (profiled)
    convx_count_kernel<<<(BB * EE + 255) / 256, 256>>>(X, ri, ro);
    scan_kernel<<<SCAN_NB, 256>>>();
    fill_kernel<<<(BB * EE + 255) / 256, 256>>>(e, ri, ro);
    gather_kernel<<<(SEG / 2) / 8, 256>>>();

    // 5/6: weight fragment packing
    convw_pack_kernel<<<(32 * NT1 * 32 + 255) / 256, 256>>>(W1, w1p_ptr, KTOT, 256);
    convw_pack_kernel<<<(32 * NT2 * 32 + 255) / 256, 256>>>(W2, w2p_ptr, 256, 256);

    // 7: fused MLP
    const int nblk = (RR + GBM - 1) / GBM;    // 782
    fused_mlp_kernel<<<nblk, 512, SMEM_BYTES>>>(b1, b2, out, RR);
}